// round 3
// baseline (speedup 1.0000x reference)
#include <cuda_runtime.h>
#include <stdint.h>

// Problem constants (fixed by the dataset).
#define Nn 20000
#define Ee 5000
#define Ff 128
#define NODE_CAP 256   // max edges per node (Binom(5000,.01): mean 50, max ~81)
#define EDGE_CAP 512   // max nodes per edge (Binom(20000,.01): mean 200, max ~260)

// ---------------- device scratch (no allocations allowed) ----------------
__device__ float g_Xw[Nn * Ff];                        // 10.24 MB (L2-resident)
__device__ float g_M[Ee * Ff];                         //  2.56 MB (L2-resident)
__device__ int   g_node_cnt[Nn];
__device__ int   g_edge_cnt[Ee];
__device__ unsigned short g_node_edges[Nn * NODE_CAP];
__device__ unsigned short g_edge_nodes[Ee * EDGE_CAP];

__device__ __forceinline__ float4 f4add(float4 a, float4 b) {
    a.x += b.x; a.y += b.y; a.z += b.z; a.w += b.w; return a;
}

// ---------------- K0: zero the edge counters only ----------------
__global__ void k_zero_counters() {
    int i = blockIdx.x * blockDim.x + threadIdx.x;
    if (i < Ee) g_edge_cnt[i] = 0;
}

// ---------------- K1: Xw = X @ W, 4x4 register micro-tile ----------------
__global__ __launch_bounds__(256) void k_xw(const float* __restrict__ X,
                                            const float* __restrict__ W) {
    __shared__ float xs[32][Ff];   // 16 KB X tile
    int tx = threadIdx.x;          // 0..31 (col group)
    int ty = threadIdx.y;          // 0..7  (row group)
    int tid = ty * 32 + tx;
    int row0 = blockIdx.x * 32;

    const float4* X4 = (const float4*)(X + (size_t)row0 * Ff);
#pragma unroll
    for (int k = 0; k < 4; k++) {
        int v = tid + k * 256;
        int r = v >> 5, c4 = v & 31;
        ((float4*)&xs[r][0])[c4] = X4[r * 32 + c4];
    }
    __syncthreads();

    const float4* W4 = (const float4*)W;
    float4 acc0 = {0,0,0,0}, acc1 = {0,0,0,0}, acc2 = {0,0,0,0}, acc3 = {0,0,0,0};
    int r0 = 4 * ty;

#pragma unroll 4
    for (int k = 0; k < Ff; k++) {
        float4 w = W4[k * 32 + tx];
        float x0 = xs[r0 + 0][k];
        float x1 = xs[r0 + 1][k];
        float x2 = xs[r0 + 2][k];
        float x3 = xs[r0 + 3][k];
        acc0.x += x0 * w.x; acc0.y += x0 * w.y; acc0.z += x0 * w.z; acc0.w += x0 * w.w;
        acc1.x += x1 * w.x; acc1.y += x1 * w.y; acc1.z += x1 * w.z; acc1.w += x1 * w.w;
        acc2.x += x2 * w.x; acc2.y += x2 * w.y; acc2.z += x2 * w.z; acc2.w += x2 * w.w;
        acc3.x += x3 * w.x; acc3.y += x3 * w.y; acc3.z += x3 * w.z; acc3.w += x3 * w.w;
    }

    float4* O4 = (float4*)g_Xw;
    int orow = row0 + r0;
    O4[(orow + 0) * 32 + tx] = acc0;
    O4[(orow + 1) * 32 + tx] = acc1;
    O4[(orow + 2) * 32 + tx] = acc2;
    O4[(orow + 3) * 32 + tx] = acc3;
}

// ---------------- K2: single pass over H, build both adjacency slabs -----
__global__ __launch_bounds__(256) void k_scan_h(const float* __restrict__ H) {
    __shared__ int s_cnt;
    int n = blockIdx.x;
    if (threadIdx.x == 0) s_cnt = 0;
    __syncthreads();

    const float4* row = (const float4*)(H + (size_t)n * Ee);
    const int nvec = Ee / 4;  // 1250
    for (int i4 = threadIdx.x; i4 < nvec; i4 += 256) {
        float4 v = row[i4];
        int ebase = i4 * 4;
        float vals[4] = {v.x, v.y, v.z, v.w};
#pragma unroll
        for (int c = 0; c < 4; c++) {
            if (vals[c] != 0.0f) {
                int e = ebase + c;
                int j = atomicAdd(&s_cnt, 1);
                if (j < NODE_CAP) g_node_edges[n * NODE_CAP + j] = (unsigned short)e;
                int k = atomicAdd(&g_edge_cnt[e], 1);
                if (k < EDGE_CAP) g_edge_nodes[e * EDGE_CAP + k] = (unsigned short)n;
            }
        }
    }
    __syncthreads();
    if (threadIdx.x == 0) g_node_cnt[n] = s_cnt;
}

// ---------------- K3: warp-per-edge gather, 8-deep MLP --------------------
// 8 warps per block, each warp owns one edge row (128 floats = 32 lanes x f4).
__global__ __launch_bounds__(256) void k_edge_gather() {
    __shared__ unsigned short s_list[8][EDGE_CAP];
    int w = threadIdx.x >> 5, l = threadIdx.x & 31;
    int e = blockIdx.x * 8 + w;
    int cnt = g_edge_cnt[e];
    int L = cnt < EDGE_CAP ? cnt : EDGE_CAP;

    for (int i = l; i < L; i += 32)
        s_list[w][i] = g_edge_nodes[e * EDGE_CAP + i];
    __syncwarp();

    const float4* Xw4 = (const float4*)g_Xw;   // row stride 32 float4
    float4 a0 = {0,0,0,0}, a1 = {0,0,0,0}, a2 = {0,0,0,0}, a3 = {0,0,0,0};
    float4 a4 = {0,0,0,0}, a5 = {0,0,0,0}, a6 = {0,0,0,0}, a7 = {0,0,0,0};

    int i = 0;
    for (; i + 8 <= L; i += 8) {
        int n0 = s_list[w][i + 0], n1 = s_list[w][i + 1];
        int n2 = s_list[w][i + 2], n3 = s_list[w][i + 3];
        int n4 = s_list[w][i + 4], n5 = s_list[w][i + 5];
        int n6 = s_list[w][i + 6], n7 = s_list[w][i + 7];
        a0 = f4add(a0, Xw4[n0 * 32 + l]);
        a1 = f4add(a1, Xw4[n1 * 32 + l]);
        a2 = f4add(a2, Xw4[n2 * 32 + l]);
        a3 = f4add(a3, Xw4[n3 * 32 + l]);
        a4 = f4add(a4, Xw4[n4 * 32 + l]);
        a5 = f4add(a5, Xw4[n5 * 32 + l]);
        a6 = f4add(a6, Xw4[n6 * 32 + l]);
        a7 = f4add(a7, Xw4[n7 * 32 + l]);
    }
    for (; i < L; i++)
        a0 = f4add(a0, Xw4[(int)s_list[w][i] * 32 + l]);

    float4 r = f4add(f4add(f4add(a0, a1), f4add(a2, a3)),
                     f4add(f4add(a4, a5), f4add(a6, a7)));
    float inv = __fdividef(1.0f, (float)cnt + 1e-12f);
    r.x *= inv; r.y *= inv; r.z *= inv; r.w *= inv;
    ((float4*)g_M)[e * 32 + l] = r;
}

// ---------------- K4: warp-per-node gather + bias + relu ------------------
__global__ __launch_bounds__(256) void k_node_gather(const float* __restrict__ bias,
                                                     float* __restrict__ out) {
    __shared__ unsigned short s_list[8][NODE_CAP];
    int w = threadIdx.x >> 5, l = threadIdx.x & 31;
    int n = blockIdx.x * 8 + w;
    int cnt = g_node_cnt[n];
    int L = cnt < NODE_CAP ? cnt : NODE_CAP;

    for (int i = l; i < L; i += 32)
        s_list[w][i] = g_node_edges[n * NODE_CAP + i];
    __syncwarp();

    const float4* M4 = (const float4*)g_M;   // row stride 32 float4
    float4 a0 = {0,0,0,0}, a1 = {0,0,0,0}, a2 = {0,0,0,0}, a3 = {0,0,0,0};
    float4 a4 = {0,0,0,0}, a5 = {0,0,0,0}, a6 = {0,0,0,0}, a7 = {0,0,0,0};

    int i = 0;
    for (; i + 8 <= L; i += 8) {
        int e0 = s_list[w][i + 0], e1 = s_list[w][i + 1];
        int e2 = s_list[w][i + 2], e3 = s_list[w][i + 3];
        int e4 = s_list[w][i + 4], e5 = s_list[w][i + 5];
        int e6 = s_list[w][i + 6], e7 = s_list[w][i + 7];
        a0 = f4add(a0, M4[e0 * 32 + l]);
        a1 = f4add(a1, M4[e1 * 32 + l]);
        a2 = f4add(a2, M4[e2 * 32 + l]);
        a3 = f4add(a3, M4[e3 * 32 + l]);
        a4 = f4add(a4, M4[e4 * 32 + l]);
        a5 = f4add(a5, M4[e5 * 32 + l]);
        a6 = f4add(a6, M4[e6 * 32 + l]);
        a7 = f4add(a7, M4[e7 * 32 + l]);
    }
    for (; i < L; i++)
        a0 = f4add(a0, M4[(int)s_list[w][i] * 32 + l]);

    float4 r = f4add(f4add(f4add(a0, a1), f4add(a2, a3)),
                     f4add(f4add(a4, a5), f4add(a6, a7)));
    float inv = __fdividef(1.0f, (float)cnt + 1e-12f);
    float4 b = ((const float4*)bias)[l];
    r.x = fmaxf(r.x * inv + b.x, 0.0f);
    r.y = fmaxf(r.y * inv + b.y, 0.0f);
    r.z = fmaxf(r.z * inv + b.z, 0.0f);
    r.w = fmaxf(r.w * inv + b.w, 0.0f);
    ((float4*)out)[n * 32 + l] = r;
}

// ---------------- launch -------------------------------------------------
extern "C" void kernel_launch(void* const* d_in, const int* in_sizes, int n_in,
                              void* d_out, int out_size) {
    const float* X = (const float*)d_in[0];
    const float* H = (const float*)d_in[1];
    const float* W = (const float*)d_in[2];
    const float* bias = (const float*)d_in[3];
    float* out = (float*)d_out;

    k_zero_counters<<<(Ee + 255) / 256, 256>>>();
    dim3 xwb(32, 8);
    k_xw<<<Nn / 32, xwb>>>(X, W);
    k_scan_h<<<Nn, 256>>>(H);
    k_edge_gather<<<Ee / 8, 256>>>();
    k_node_gather<<<Nn / 8, 256>>>(bias, out);
}